// round 13
// baseline (speedup 1.0000x reference)
#include <cuda_runtime.h>
#include <math.h>
#include <stdint.h>

#define N_ATOMS 10000
#define N_PAIRS 320000
#define PB 4   // pairs per warp batch in k_pairs

// ---------------- scratch (static device globals; no runtime alloc) ----------
// A/B layout (fp32): [atom][b2*128 + c*2 + (b&1)] -> coalesced per-lane float4
__device__ __align__(16) float g_A[N_ATOMS * 640];
__device__ __align__(16) float g_B[N_ATOMS * 640];
__device__ __align__(16) float g_p1in[N_ATOMS * 64];
__device__ __align__(16) float g_p1scat[N_ATOMS * 128];
__device__ __align__(16) float g_p3acc[N_ATOMS * 192];
// pair grouping
__device__ int g_cnt[N_ATOMS];
__device__ int g_cur[N_ATOMS];
__device__ int g_startA[N_ATOMS];
__device__ int g_perm[N_PAIRS];

// ---------------- helpers ----------------------------------------------------
__device__ __forceinline__ float fast_tanh(float x) {
    float e = __expf(2.0f * x);
    return 1.0f - __fdividef(2.0f, e + 1.0f);
}
__device__ __forceinline__ float tanh_hw(float x) {
    float y;
    asm("tanh.approx.f32 %0, %1;" : "=f"(y) : "f"(x));
    return y;
}

// ---------------- grouping kernels -------------------------------------------
__global__ void k_hzero() {
    int t = blockIdx.x * blockDim.x + threadIdx.x;
    if (t < N_ATOMS) { g_cnt[t] = 0; g_cur[t] = 0; }
}
__global__ void k_hist(const int* __restrict__ ind2) {
    int p = blockIdx.x * blockDim.x + threadIdx.x;
    if (p < N_PAIRS) atomicAdd(&g_cnt[__ldg(&ind2[2 * p])], 1);
}
__global__ void k_scan() {
    __shared__ int s_part[1024];
    int tid = threadIdx.x;
    int base = tid * 10;
    int local[10];
    int sum = 0;
    #pragma unroll
    for (int u = 0; u < 10; u++) {
        int idx = base + u;
        int c = (idx < N_ATOMS) ? g_cnt[idx] : 0;
        local[u] = sum;
        sum += c;
    }
    s_part[tid] = sum;
    __syncthreads();
    for (int off = 1; off < 1024; off <<= 1) {
        int v = (tid >= off) ? s_part[tid - off] : 0;
        __syncthreads();
        s_part[tid] += v;
        __syncthreads();
    }
    int excl = (tid > 0) ? s_part[tid - 1] : 0;
    #pragma unroll
    for (int u = 0; u < 10; u++) {
        int idx = base + u;
        if (idx < N_ATOMS) g_startA[idx] = excl + local[u];
    }
}
__global__ void k_scatter(const int* __restrict__ ind2) {
    int p = blockIdx.x * blockDim.x + threadIdx.x;
    if (p < N_PAIRS) {
        int i = __ldg(&ind2[2 * p]);
        int pos = g_startA[i] + atomicAdd(&g_cur[i], 1);
        g_perm[pos] = p;
    }
}

// ---------------- kernel AB1: p1_in = tanh(tanh(p1@W1+b1)@W2+b2) -> global ---
__global__ void k_ab1(const float* __restrict__ p1,
                      const float* __restrict__ W1, const float* __restrict__ b1,
                      const float* __restrict__ W2, const float* __restrict__ b2) {
    __shared__ float s_x[32][64];
    __shared__ float s_t[32][64];
    int tid = threadIdx.x;
    int a_base = blockIdx.x * 32;

    for (int e = tid; e < 32 * 64; e += 256) {
        int a = e >> 6, c = e & 63;
        int atom = a_base + a;
        s_x[a][c] = (atom < N_ATOMS) ? __ldg(&p1[atom * 64 + c]) : 0.f;
    }
    __syncthreads();
    for (int e = tid; e < 32 * 64; e += 256) {
        int a = e >> 6, o = e & 63;
        float acc = __ldg(&b1[o]);
        #pragma unroll 8
        for (int c = 0; c < 64; c++)
            acc = fmaf(s_x[a][c], __ldg(&W1[c * 64 + o]), acc);
        s_t[a][o] = fast_tanh(acc);
    }
    __syncthreads();
    for (int e = tid; e < 32 * 64; e += 256) {
        int a = e >> 6, o = e & 63;
        int atom = a_base + a;
        if (atom >= N_ATOMS) continue;
        float acc = __ldg(&b2[o]);
        #pragma unroll 8
        for (int c = 0; c < 64; c++)
            acc = fmaf(s_t[a][c], __ldg(&W2[c * 64 + o]), acc);
        g_p1in[atom * 64 + o] = fast_tanh(acc);
    }
}

// ---------------- kernel AB2: tiled GEMM -> A/B tables (fp32, bias folded) ----
__global__ void __launch_bounds__(256, 4) k_ab2(const float* __restrict__ piW,
                                                const float* __restrict__ pib) {
    __shared__ __align__(16) float s_a[64 * 132];   // [k][atom], pad 132
    __shared__ __align__(16) float s_w[64 * 64];    // [k][n_local] permuted

    int tid = threadIdx.x;
    int tx = tid & 15;
    int ty = tid >> 4;
    int at = blockIdx.x;
    int ct = blockIdx.y;
    int a_base = at * 128;
    int table = ct / 10;
    int nb_base = (ct - table * 10) * 64;

    for (int l = tid; l < 128 * 16; l += 256) {
        int a = l >> 4, kq = l & 15;
        int atom = a_base + a;
        float4 v = (atom < N_ATOMS)
            ? __ldg((const float4*)(g_p1in + (size_t)atom * 64) + kq)
            : make_float4(0.f, 0.f, 0.f, 0.f);
        s_a[(4 * kq + 0) * 132 + a] = v.x;
        s_a[(4 * kq + 1) * 132 + a] = v.y;
        s_a[(4 * kq + 2) * 132 + a] = v.z;
        s_a[(4 * kq + 3) * 132 + a] = v.w;
    }
    for (int l = tid; l < 64 * 64; l += 256) {
        int k = l >> 6, nl = l & 63;
        int nb = nb_base + nl;
        int b2i = nb >> 7;
        int rr = nb & 127;
        int c = rr >> 1;
        int e = rr & 1;
        s_w[l] = __ldg(&piW[(size_t)(k + 64 * table) * 640 + c * 10 + 2 * b2i + e]);
    }
    __syncthreads();

    float4 acc[8];
    #pragma unroll
    for (int u = 0; u < 8; u++) acc[u] = make_float4(0.f, 0.f, 0.f, 0.f);

    const float4* sa4 = (const float4*)s_a;
    const float4* sw4 = (const float4*)s_w;
    #pragma unroll 4
    for (int k = 0; k < 64; k++) {
        float4 w = sw4[k * 16 + tx];
        float4 a0 = sa4[k * 33 + 2 * ty];
        float4 a1 = sa4[k * 33 + 2 * ty + 1];
        float av[8] = {a0.x, a0.y, a0.z, a0.w, a1.x, a1.y, a1.z, a1.w};
        #pragma unroll
        for (int u = 0; u < 8; u++) {
            acc[u].x = fmaf(av[u], w.x, acc[u].x);
            acc[u].y = fmaf(av[u], w.y, acc[u].y);
            acc[u].z = fmaf(av[u], w.z, acc[u].z);
            acc[u].w = fmaf(av[u], w.w, acc[u].w);
        }
    }

    float4 bias = make_float4(0.f, 0.f, 0.f, 0.f);
    if (table == 0) {
        int nb = nb_base + 4 * tx;
        int b2i = nb >> 7;
        int rr = nb & 127;
        int c = rr >> 1;
        bias.x = __ldg(&pib[c * 10 + 2 * b2i]);
        bias.y = __ldg(&pib[c * 10 + 2 * b2i + 1]);
        bias.z = __ldg(&pib[(c + 1) * 10 + 2 * b2i]);
        bias.w = __ldg(&pib[(c + 1) * 10 + 2 * b2i + 1]);
    }

    float* outT = table ? g_B : g_A;
    #pragma unroll
    for (int u = 0; u < 8; u++) {
        int atom = a_base + 8 * ty + u;
        if (atom < N_ATOMS) {
            float4 r;
            r.x = acc[u].x + bias.x;
            r.y = acc[u].y + bias.y;
            r.z = acc[u].z + bias.z;
            r.w = acc[u].w + bias.w;
            *(float4*)(outT + (size_t)atom * 640 + nb_base + 4 * tx) = r;
        }
    }
}

// ---------------- kernel P: grouped per-atom main body ------------------------
// persistent blocks; each block processes whole atoms (all pairs with i=atom).
// A[i] staged in smem; p1/p3 segment sums accumulated in regs -> block reduce
// -> single store. No global atomics at all.
__global__ void __launch_bounds__(256, 3) k_pairs(
        const int* __restrict__ ind2,
        const float* __restrict__ basis,
        const float* __restrict__ d3,
        const float* __restrict__ fc_edge,
        const float* __restrict__ p3,
        const float* __restrict__ ii_W) {
    __shared__ float4 s_ii4[64 * 32];                      // 32 KB
    __shared__ __align__(16) float s_A[640];               // 2.5 KB
    __shared__ __align__(16) float s_s[8][PB][64];         // 8 KB
    __shared__ float4 s_i1b[8][PB][16];                    // 8 KB
    __shared__ __align__(16) float s_red1[8][128];         // 4 KB
    __shared__ __align__(16) float s_red3[8][192];         // 6 KB
    __shared__ float s_v[3];

    int tid = threadIdx.x;
    int lane = tid & 31;
    int wid = tid >> 5;

    for (int t = tid; t < 64 * 32; t += 256)
        s_ii4[t] = __ldg(((const float4*)ii_W) + t);

    for (int atom = blockIdx.x; atom < N_ATOMS; atom += gridDim.x) {
        __syncthreads();   // covers ii_W staging (1st iter) + smem reuse
        int start = __ldg(&g_startA[atom]);
        int count = __ldg(&g_cnt[atom]);

        // stage A[atom] (bias already folded)
        for (int t = tid; t < 160; t += 256)
            ((float4*)s_A)[t] = __ldg((const float4*)(g_A + (size_t)atom * 640) + t);

        // v = sum over group of d3*fc
        float vx = 0.f, vy = 0.f, vz = 0.f;
        for (int q = tid; q < count; q += 256) {
            int p = __ldg(&g_perm[start + q]);
            float fc = __ldg(&fc_edge[p]);
            vx = fmaf(__ldg(&d3[3 * p + 0]), fc, vx);
            vy = fmaf(__ldg(&d3[3 * p + 1]), fc, vy);
            vz = fmaf(__ldg(&d3[3 * p + 2]), fc, vz);
        }
        #pragma unroll
        for (int off = 16; off; off >>= 1) {
            vx += __shfl_xor_sync(0xffffffffu, vx, off);
            vy += __shfl_xor_sync(0xffffffffu, vy, off);
            vz += __shfl_xor_sync(0xffffffffu, vz, off);
        }
        if (lane == 0) {
            s_red1[wid][0] = vx; s_red1[wid][1] = vy; s_red1[wid][2] = vz;
        }
        __syncthreads();
        if (tid < 3) {
            float s = 0.f;
            #pragma unroll
            for (int w = 0; w < 8; w++) s += s_red1[w][tid];
            s_v[tid] = s;
        }
        __syncthreads();
        float v0 = s_v[0], v1 = s_v[1], v2 = s_v[2];

        float4 accP1 = make_float4(0.f, 0.f, 0.f, 0.f);
        float4 accP3a = make_float4(0.f, 0.f, 0.f, 0.f);
        float4 accP3b = make_float4(0.f, 0.f, 0.f, 0.f);

        int nr = (count + 31) >> 5;
        for (int r = 0; r < nr; r++) {
            int qb = (r << 5) + wid * PB;
            int pr[PB], jj[PB];
            bool act[PB];
            #pragma unroll
            for (int pp = 0; pp < PB; pp++) {
                int q = qb + pp;
                act[pp] = (q < count);
                pr[pp] = act[pp] ? __ldg(&g_perm[start + q]) : 0;
                jj[pp] = act[pp] ? __ldg(&ind2[2 * pr[pp] + 1]) : 0;
            }

            // ---- phase A: s = sum_b tanh(A[i]+B[j]) * basis
            #pragma unroll
            for (int pp = 0; pp < PB; pp++) {
                if (!act[pp]) continue;
                int p = pr[pp];
                const float2* basf = (const float2*)(basis + (size_t)p * 10);
                const float4* Ar = (const float4*)s_A;
                const float4* Br = (const float4*)(g_B + (size_t)jj[pp] * 640);
                float sum0 = 0.f, sum1 = 0.f;
                #pragma unroll
                for (int b2i = 0; b2i < 5; b2i++) {
                    float4 a4 = Ar[b2i * 32 + lane];
                    float4 b4 = __ldg(Br + b2i * 32 + lane);
                    float2 bb = __ldg(basf + b2i);
                    float t0 = tanh_hw(a4.x + b4.x);
                    float t1 = tanh_hw(a4.y + b4.y);
                    float t2 = tanh_hw(a4.z + b4.z);
                    float t3 = tanh_hw(a4.w + b4.w);
                    sum0 = fmaf(t0, bb.x, sum0);
                    sum0 = fmaf(t1, bb.y, sum0);
                    sum1 = fmaf(t2, bb.x, sum1);
                    sum1 = fmaf(t3, bb.y, sum1);
                }
                *(float2*)&s_s[wid][pp][2 * lane] = make_float2(sum0, sum1);
            }
            __syncwarp();

            // ---- phase B: i_pair = tanh(s @ ii_W), weights shared across PB
            float4 accB[PB];
            #pragma unroll
            for (int pp = 0; pp < PB; pp++) accB[pp] = make_float4(0.f, 0.f, 0.f, 0.f);
            #pragma unroll
            for (int c4 = 0; c4 < 16; c4++) {
                float4 w0 = s_ii4[(4 * c4 + 0) * 32 + lane];
                float4 w1 = s_ii4[(4 * c4 + 1) * 32 + lane];
                float4 w2 = s_ii4[(4 * c4 + 2) * 32 + lane];
                float4 w3 = s_ii4[(4 * c4 + 3) * 32 + lane];
                #pragma unroll
                for (int pp = 0; pp < PB; pp++) {
                    float4 sv = ((const float4*)s_s[wid][pp])[c4];
                    accB[pp].x = fmaf(sv.x, w0.x, accB[pp].x); accB[pp].y = fmaf(sv.x, w0.y, accB[pp].y);
                    accB[pp].z = fmaf(sv.x, w0.z, accB[pp].z); accB[pp].w = fmaf(sv.x, w0.w, accB[pp].w);
                    accB[pp].x = fmaf(sv.y, w1.x, accB[pp].x); accB[pp].y = fmaf(sv.y, w1.y, accB[pp].y);
                    accB[pp].z = fmaf(sv.y, w1.z, accB[pp].z); accB[pp].w = fmaf(sv.y, w1.w, accB[pp].w);
                    accB[pp].x = fmaf(sv.z, w2.x, accB[pp].x); accB[pp].y = fmaf(sv.z, w2.y, accB[pp].y);
                    accB[pp].z = fmaf(sv.z, w2.z, accB[pp].z); accB[pp].w = fmaf(sv.z, w2.w, accB[pp].w);
                    accB[pp].x = fmaf(sv.w, w3.x, accB[pp].x); accB[pp].y = fmaf(sv.w, w3.y, accB[pp].y);
                    accB[pp].z = fmaf(sv.w, w3.z, accB[pp].z); accB[pp].w = fmaf(sv.w, w3.w, accB[pp].w);
                }
            }
            #pragma unroll
            for (int pp = 0; pp < PB; pp++) {
                float4 ip;
                ip.x = fast_tanh(accB[pp].x);
                ip.y = fast_tanh(accB[pp].y);
                ip.z = fast_tanh(accB[pp].z);
                ip.w = fast_tanh(accB[pp].w);
                if (act[pp]) {
                    accP1.x += ip.x; accP1.y += ip.y;
                    accP1.z += ip.z; accP1.w += ip.w;
                }
                if (lane >= 16) s_i1b[wid][pp][lane - 16] = ip;
            }
            __syncwarp();

            // ---- phases C+D per pair (accumulate p3 in regs)
            #pragma unroll
            for (int pp = 0; pp < PB; pp++) {
                if (!act[pp]) continue;
                int p = pr[pp];
                int j = jj[pp];
                float d0 = __ldg(&d3[3 * p + 0]);
                float d1 = __ldg(&d3[3 * p + 1]);
                float d2 = __ldg(&d3[3 * p + 2]);
                float fc = __ldg(&fc_edge[p]);
                float proj = v0 * d0 + v1 * d1 + v2 * d2;
                float wx = v0 - proj * d0, wy = v1 - proj * d1, wz = v2 - proj * d2;
                float w2 = wx * wx + wy * wy + wz * wz;
                float g_deg = __fdividef(w2, w2 + 1e-4f);
                float rs = rsqrtf(w2 + 1e-6f);
                float tb = g_deg * fc * fc;
                float sc = rs * g_deg * tb;
                float term0 = d0 + wx * sc;
                float term1 = d1 + wy * sc;
                float term2 = d2 + wz * sc;

                const float4* p3j = (const float4*)(p3 + (size_t)j * 192);
                // it = 0: t = lane (0..31)
                {
                    int x = lane >> 4;
                    int m = lane & 15;
                    float4 gg = s_i1b[wid][pp][m];
                    float4 pj = __ldg(&p3j[x * 16 + m]);
                    float tm = (x == 0) ? term0 : term1;
                    accP3a.x = fmaf(gg.x, pj.x + tm, accP3a.x);
                    accP3a.y = fmaf(gg.y, pj.y + tm, accP3a.y);
                    accP3a.z = fmaf(gg.z, pj.z + tm, accP3a.z);
                    accP3a.w = fmaf(gg.w, pj.w + tm, accP3a.w);
                }
                // it = 1: t = lane+32 (32..47 valid -> lane<16)
                if (lane < 16) {
                    int m = lane;         // t & 15 with t = lane+32, x = 2
                    float4 gg = s_i1b[wid][pp][m];
                    float4 pj = __ldg(&p3j[2 * 16 + m]);
                    accP3b.x = fmaf(gg.x, pj.x + term2, accP3b.x);
                    accP3b.y = fmaf(gg.y, pj.y + term2, accP3b.y);
                    accP3b.z = fmaf(gg.z, pj.z + term2, accP3b.z);
                    accP3b.w = fmaf(gg.w, pj.w + term2, accP3b.w);
                }
            }
        }

        // dump per-warp accumulators and block-reduce -> single store
        ((float4*)s_red1[wid])[lane] = accP1;
        ((float4*)s_red3[wid])[lane] = accP3a;
        if (lane < 16) ((float4*)s_red3[wid])[lane + 32] = accP3b;
        __syncthreads();
        if (tid < 80) {
            if (tid < 32) {
                float4 s = make_float4(0.f, 0.f, 0.f, 0.f);
                #pragma unroll
                for (int w = 0; w < 8; w++) {
                    float4 t = ((const float4*)s_red1[w])[tid];
                    s.x += t.x; s.y += t.y; s.z += t.z; s.w += t.w;
                }
                ((float4*)(g_p1scat + (size_t)atom * 128))[tid] = s;
            } else {
                int u = tid - 32;
                float4 s = make_float4(0.f, 0.f, 0.f, 0.f);
                #pragma unroll
                for (int w = 0; w < 8; w++) {
                    float4 t = ((const float4*)s_red3[w])[u];
                    s.x += t.x; s.y += t.y; s.z += t.z; s.w += t.w;
                }
                ((float4*)(g_p3acc + (size_t)atom * 192))[u] = s;
            }
        }
    }
}

// ---------------- kernel F: atom finalize (32 atoms/block, 8-atom reg block) --
__global__ void __launch_bounds__(256) k_final(
        const float* __restrict__ postW1,
        const float* __restrict__ postW2,
        const float* __restrict__ eqW,
        const float* __restrict__ q1W1,
        const float* __restrict__ q1b1,
        const float* __restrict__ q1W2,
        const float* __restrict__ q1b2,
        float* __restrict__ out) {
    __shared__ float s_cat[32][128];
    __shared__ float s_acc[32][192];
    __shared__ float s_b[32][64];

    int tid = threadIdx.x;
    int o = tid & 63;
    int g = tid >> 6;
    int a_base = blockIdx.x * 32;
    float4 z4 = make_float4(0.f, 0.f, 0.f, 0.f);

    for (int e = tid; e < 32 * 32; e += 256) {
        int a = e >> 5, c4 = e & 31;
        int atom = a_base + a;
        ((float4*)s_cat[a])[c4] = (atom < N_ATOMS)
            ? __ldg((const float4*)(g_p1scat + (size_t)atom * 128) + c4) : z4;
    }
    for (int e = tid; e < 32 * 48; e += 256) {
        int a = e / 48, c4 = e % 48;
        int atom = a_base + a;
        ((float4*)s_acc[a])[c4] = (atom < N_ATOMS)
            ? __ldg((const float4*)(g_p3acc + (size_t)atom * 192) + c4) : z4;
    }
    __syncthreads();

    // phase1: t1 = tanh(scat @ postW1) -> s_b
    {
        float accv[8];
        #pragma unroll
        for (int u = 0; u < 8; u++) accv[u] = 0.f;
        for (int c = 0; c < 128; c++) {
            float w = __ldg(&postW1[c * 64 + o]);
            #pragma unroll
            for (int u = 0; u < 8; u++)
                accv[u] = fmaf(s_cat[8 * g + u][c], w, accv[u]);
        }
        __syncthreads();
        #pragma unroll
        for (int u = 0; u < 8; u++) s_b[8 * g + u][o] = fast_tanh(accv[u]);
    }
    __syncthreads();

    // phase2: p1_new = tanh(t1 @ postW2) -> s_cat[:, 0:64]
    {
        float accv[8];
        #pragma unroll
        for (int u = 0; u < 8; u++) accv[u] = 0.f;
        for (int c = 0; c < 64; c++) {
            float w = __ldg(&postW2[c * 64 + o]);
            #pragma unroll
            for (int u = 0; u < 8; u++)
                accv[u] = fmaf(s_b[8 * g + u][c], w, accv[u]);
        }
        #pragma unroll
        for (int u = 0; u < 8; u++) s_cat[8 * g + u][o] = fast_tanh(accv[u]);
    }

    // phase3: p3n (regs) + dotted -> s_cat[:, 64:128]
    float p3n[3][8];
    #pragma unroll
    for (int x = 0; x < 3; x++) {
        float accv[8];
        #pragma unroll
        for (int u = 0; u < 8; u++) accv[u] = 0.f;
        for (int c = 0; c < 64; c++) {
            float w = __ldg(&eqW[c * 64 + o]);
            #pragma unroll
            for (int u = 0; u < 8; u++)
                accv[u] = fmaf(s_acc[8 * g + u][x * 64 + c], w, accv[u]);
        }
        #pragma unroll
        for (int u = 0; u < 8; u++) p3n[x][u] = accv[u];
    }
    #pragma unroll
    for (int u = 0; u < 8; u++)
        s_cat[8 * g + u][64 + o] = p3n[0][u] * p3n[0][u] +
                                   p3n[1][u] * p3n[1][u] +
                                   p3n[2][u] * p3n[2][u];
    __syncthreads();

    // phase4: h2a = tanh(cat @ q1W1 + b1) -> s_b
    {
        float accv[8];
        float bias = __ldg(&q1b1[o]);
        #pragma unroll
        for (int u = 0; u < 8; u++) accv[u] = bias;
        for (int c = 0; c < 128; c++) {
            float w = __ldg(&q1W1[c * 64 + o]);
            #pragma unroll
            for (int u = 0; u < 8; u++)
                accv[u] = fmaf(s_cat[8 * g + u][c], w, accv[u]);
        }
        __syncthreads();
        #pragma unroll
        for (int u = 0; u < 8; u++) s_b[8 * g + u][o] = fast_tanh(accv[u]);
    }
    __syncthreads();

    // phase5: h2 = tanh(h2a @ q1W2 + b2); write outputs
    {
        float h0[8], h1[8];
        float bias0 = __ldg(&q1b2[o]);
        float bias1 = __ldg(&q1b2[o + 64]);
        #pragma unroll
        for (int u = 0; u < 8; u++) { h0[u] = bias0; h1[u] = bias1; }
        for (int c = 0; c < 64; c++) {
            float w0 = __ldg(&q1W2[c * 128 + o]);
            float w1 = __ldg(&q1W2[c * 128 + o + 64]);
            #pragma unroll
            for (int u = 0; u < 8; u++) {
                float v = s_b[8 * g + u][c];
                h0[u] = fmaf(v, w0, h0[u]);
                h1[u] = fmaf(v, w1, h1[u]);
            }
        }
        #pragma unroll
        for (int u = 0; u < 8; u++) {
            int atom = a_base + 8 * g + u;
            if (atom < N_ATOMS) {
                float g1 = fast_tanh(h0[u]);
                float g3 = fast_tanh(h1[u]);
                out[(size_t)atom * 64 + o] = g1;
                float* o3 = out + (size_t)N_ATOMS * 64 + (size_t)atom * 192;
                #pragma unroll
                for (int x = 0; x < 3; x++)
                    o3[x * 64 + o] = p3n[x][u] * g3;
            }
        }
    }
}

// ---------------- launch ------------------------------------------------------
extern "C" void kernel_launch(void* const* d_in, const int* in_sizes, int n_in,
                              void* d_out, int out_size) {
    const int*   ind2    = (const int*)d_in[0];
    const float* p1      = (const float*)d_in[1];
    const float* p3      = (const float*)d_in[2];
    const float* basis   = (const float*)d_in[3];
    const float* d3      = (const float*)d_in[4];
    const float* fc_edge = (const float*)d_in[5];
    const float* ppreW1  = (const float*)d_in[6];
    const float* ppreb1  = (const float*)d_in[7];
    const float* ppreW2  = (const float*)d_in[8];
    const float* ppreb2  = (const float*)d_in[9];
    const float* piW     = (const float*)d_in[10];
    const float* pib     = (const float*)d_in[11];
    const float* iiW     = (const float*)d_in[12];
    const float* postW1  = (const float*)d_in[13];
    const float* postW2  = (const float*)d_in[14];
    const float* eqW     = (const float*)d_in[15];
    const float* q1W1    = (const float*)d_in[16];
    const float* q1b1    = (const float*)d_in[17];
    const float* q1W2    = (const float*)d_in[18];
    const float* q1b2    = (const float*)d_in[19];
    float* out = (float*)d_out;

    k_hzero<<<(N_ATOMS + 255) / 256, 256>>>();
    k_hist<<<(N_PAIRS + 255) / 256, 256>>>(ind2);
    k_scan<<<1, 1024>>>();
    k_scatter<<<(N_PAIRS + 255) / 256, 256>>>(ind2);
    k_ab1<<<(N_ATOMS + 31) / 32, 256>>>(p1, ppreW1, ppreb1, ppreW2, ppreb2);
    {
        dim3 grid((N_ATOMS + 127) / 128, 20);
        k_ab2<<<grid, 256>>>(piW, pib);
    }
    k_pairs<<<444, 256>>>(ind2, basis, d3, fc_edge, p3, iiW);
    k_final<<<(N_ATOMS + 31) / 32, 256>>>(postW1, postW2, eqW, q1W1, q1b1, q1W2, q1b2, out);
}

// round 14
// speedup vs baseline: 1.2399x; 1.2399x over previous
#include <cuda_runtime.h>
#include <math.h>
#include <stdint.h>

#define N_ATOMS 10000
#define N_PAIRS 320000
#define PB 4   // pairs per warp batch in k_pairs

// ---------------- scratch (static device globals; no runtime alloc) ----------
// A/B layout (fp32): [atom][b2*128 + c*2 + (b&1)] -> coalesced per-lane float4
__device__ __align__(16) float g_A[N_ATOMS * 640];
__device__ __align__(16) float g_B[N_ATOMS * 640];
__device__ __align__(16) float g_p1in[N_ATOMS * 64];
__device__ __align__(16) float g_v[N_ATOMS * 4];
__device__ __align__(16) float g_p1scat[N_ATOMS * 128];
__device__ __align__(16) float g_p3acc[N_ATOMS * 192];
// pair grouping
__device__ int g_cnt[N_ATOMS];
__device__ int g_cur[N_ATOMS];
__device__ int g_startA[N_ATOMS];
__device__ int g_perm[N_PAIRS];

// ---------------- helpers ----------------------------------------------------
__device__ __forceinline__ float fast_tanh(float x) {
    float e = __expf(2.0f * x);
    return 1.0f - __fdividef(2.0f, e + 1.0f);
}
__device__ __forceinline__ float tanh_hw(float x) {
    float y;
    asm("tanh.approx.f32 %0, %1;" : "=f"(y) : "f"(x));
    return y;
}
__device__ __forceinline__ void red_add_v4(float* addr, float4 v) {
    asm volatile("red.global.add.v4.f32 [%0], {%1,%2,%3,%4};"
                 :: "l"(addr), "f"(v.x), "f"(v.y), "f"(v.z), "f"(v.w)
                 : "memory");
}

// ---------------- grouping kernels -------------------------------------------
__global__ void k_hzero() {
    int t = blockIdx.x * blockDim.x + threadIdx.x;
    if (t < N_ATOMS) { g_cnt[t] = 0; g_cur[t] = 0; }
}
__global__ void k_hist(const int* __restrict__ ind2) {
    int p = blockIdx.x * blockDim.x + threadIdx.x;
    if (p < N_PAIRS) atomicAdd(&g_cnt[__ldg(&ind2[2 * p])], 1);
}
__global__ void k_scan() {
    __shared__ int s_part[1024];
    int tid = threadIdx.x;
    int base = tid * 10;
    int local[10];
    int sum = 0;
    #pragma unroll
    for (int u = 0; u < 10; u++) {
        int idx = base + u;
        int c = (idx < N_ATOMS) ? g_cnt[idx] : 0;
        local[u] = sum;
        sum += c;
    }
    s_part[tid] = sum;
    __syncthreads();
    for (int off = 1; off < 1024; off <<= 1) {
        int v = (tid >= off) ? s_part[tid - off] : 0;
        __syncthreads();
        s_part[tid] += v;
        __syncthreads();
    }
    int excl = (tid > 0) ? s_part[tid - 1] : 0;
    #pragma unroll
    for (int u = 0; u < 10; u++) {
        int idx = base + u;
        if (idx < N_ATOMS) g_startA[idx] = excl + local[u];
    }
}
__global__ void k_scatter(const int* __restrict__ ind2) {
    int p = blockIdx.x * blockDim.x + threadIdx.x;
    if (p < N_PAIRS) {
        int i = __ldg(&ind2[2 * p]);
        int pos = g_startA[i] + atomicAdd(&g_cur[i], 1);
        g_perm[pos] = p;
    }
}

// ---------------- kernel 0: zero accumulators --------------------------------
__global__ void k_zero() {
    int idx = blockIdx.x * blockDim.x + threadIdx.x;
    int stride = gridDim.x * blockDim.x;
    float4 z = make_float4(0.f, 0.f, 0.f, 0.f);
    float4* a = (float4*)g_p1scat;
    for (int i = idx; i < N_ATOMS * 32; i += stride) a[i] = z;
    float4* b = (float4*)g_p3acc;
    for (int i = idx; i < N_ATOMS * 48; i += stride) b[i] = z;
    float4* c = (float4*)g_v;
    for (int i = idx; i < N_ATOMS; i += stride) c[i] = z;
}

// ---------------- kernel V: v = segment_sum(d3 * fc, i) ----------------------
__global__ void k_vscat(const int* __restrict__ ind2,
                        const float* __restrict__ d3,
                        const float* __restrict__ fc_edge) {
    int p = blockIdx.x * blockDim.x + threadIdx.x;
    if (p >= N_PAIRS) return;
    int2 ij = __ldg((const int2*)ind2 + p);
    float fc = __ldg(&fc_edge[p]);
    float4 val;
    val.x = __ldg(&d3[3 * p + 0]) * fc;
    val.y = __ldg(&d3[3 * p + 1]) * fc;
    val.z = __ldg(&d3[3 * p + 2]) * fc;
    val.w = 0.f;
    red_add_v4(&g_v[4 * ij.x], val);
}

// ---------------- kernel AB1: p1_in = tanh(tanh(p1@W1+b1)@W2+b2) -> global ---
__global__ void k_ab1(const float* __restrict__ p1,
                      const float* __restrict__ W1, const float* __restrict__ b1,
                      const float* __restrict__ W2, const float* __restrict__ b2) {
    __shared__ float s_x[32][64];
    __shared__ float s_t[32][64];
    int tid = threadIdx.x;
    int a_base = blockIdx.x * 32;

    for (int e = tid; e < 32 * 64; e += 256) {
        int a = e >> 6, c = e & 63;
        int atom = a_base + a;
        s_x[a][c] = (atom < N_ATOMS) ? __ldg(&p1[atom * 64 + c]) : 0.f;
    }
    __syncthreads();
    for (int e = tid; e < 32 * 64; e += 256) {
        int a = e >> 6, o = e & 63;
        float acc = __ldg(&b1[o]);
        #pragma unroll 8
        for (int c = 0; c < 64; c++)
            acc = fmaf(s_x[a][c], __ldg(&W1[c * 64 + o]), acc);
        s_t[a][o] = fast_tanh(acc);
    }
    __syncthreads();
    for (int e = tid; e < 32 * 64; e += 256) {
        int a = e >> 6, o = e & 63;
        int atom = a_base + a;
        if (atom >= N_ATOMS) continue;
        float acc = __ldg(&b2[o]);
        #pragma unroll 8
        for (int c = 0; c < 64; c++)
            acc = fmaf(s_t[a][c], __ldg(&W2[c * 64 + o]), acc);
        g_p1in[atom * 64 + o] = fast_tanh(acc);
    }
}

// ---------------- kernel AB2: tiled GEMM -> A/B tables (fp32, bias folded) ----
__global__ void __launch_bounds__(256, 4) k_ab2(const float* __restrict__ piW,
                                                const float* __restrict__ pib) {
    __shared__ __align__(16) float s_a[64 * 132];   // [k][atom], pad 132
    __shared__ __align__(16) float s_w[64 * 64];    // [k][n_local] permuted

    int tid = threadIdx.x;
    int tx = tid & 15;
    int ty = tid >> 4;
    int at = blockIdx.x;
    int ct = blockIdx.y;
    int a_base = at * 128;
    int table = ct / 10;
    int nb_base = (ct - table * 10) * 64;

    for (int l = tid; l < 128 * 16; l += 256) {
        int a = l >> 4, kq = l & 15;
        int atom = a_base + a;
        float4 v = (atom < N_ATOMS)
            ? __ldg((const float4*)(g_p1in + (size_t)atom * 64) + kq)
            : make_float4(0.f, 0.f, 0.f, 0.f);
        s_a[(4 * kq + 0) * 132 + a] = v.x;
        s_a[(4 * kq + 1) * 132 + a] = v.y;
        s_a[(4 * kq + 2) * 132 + a] = v.z;
        s_a[(4 * kq + 3) * 132 + a] = v.w;
    }
    for (int l = tid; l < 64 * 64; l += 256) {
        int k = l >> 6, nl = l & 63;
        int nb = nb_base + nl;
        int b2i = nb >> 7;
        int rr = nb & 127;
        int c = rr >> 1;
        int e = rr & 1;
        s_w[l] = __ldg(&piW[(size_t)(k + 64 * table) * 640 + c * 10 + 2 * b2i + e]);
    }
    __syncthreads();

    float4 acc[8];
    #pragma unroll
    for (int u = 0; u < 8; u++) acc[u] = make_float4(0.f, 0.f, 0.f, 0.f);

    const float4* sa4 = (const float4*)s_a;
    const float4* sw4 = (const float4*)s_w;
    #pragma unroll 4
    for (int k = 0; k < 64; k++) {
        float4 w = sw4[k * 16 + tx];
        float4 a0 = sa4[k * 33 + 2 * ty];
        float4 a1 = sa4[k * 33 + 2 * ty + 1];
        float av[8] = {a0.x, a0.y, a0.z, a0.w, a1.x, a1.y, a1.z, a1.w};
        #pragma unroll
        for (int u = 0; u < 8; u++) {
            acc[u].x = fmaf(av[u], w.x, acc[u].x);
            acc[u].y = fmaf(av[u], w.y, acc[u].y);
            acc[u].z = fmaf(av[u], w.z, acc[u].z);
            acc[u].w = fmaf(av[u], w.w, acc[u].w);
        }
    }

    float4 bias = make_float4(0.f, 0.f, 0.f, 0.f);
    if (table == 0) {
        int nb = nb_base + 4 * tx;
        int b2i = nb >> 7;
        int rr = nb & 127;
        int c = rr >> 1;
        bias.x = __ldg(&pib[c * 10 + 2 * b2i]);
        bias.y = __ldg(&pib[c * 10 + 2 * b2i + 1]);
        bias.z = __ldg(&pib[(c + 1) * 10 + 2 * b2i]);
        bias.w = __ldg(&pib[(c + 1) * 10 + 2 * b2i + 1]);
    }

    float* outT = table ? g_B : g_A;
    #pragma unroll
    for (int u = 0; u < 8; u++) {
        int atom = a_base + 8 * ty + u;
        if (atom < N_ATOMS) {
            float4 r;
            r.x = acc[u].x + bias.x;
            r.y = acc[u].y + bias.y;
            r.z = acc[u].z + bias.z;
            r.w = acc[u].w + bias.w;
            *(float4*)(outT + (size_t)atom * 640 + nb_base + 4 * tx) = r;
        }
    }
}

// ---------------- kernel P: pair-parallel, i-sorted order, merged atomics -----
// warp handles PB=4 consecutive sorted pairs; 8 warps/block; grid-stride
__global__ void __launch_bounds__(256, 4) k_pairs(
        const int* __restrict__ ind2,
        const float* __restrict__ basis,
        const float* __restrict__ d3,
        const float* __restrict__ fc_edge,
        const float* __restrict__ p3,
        const float* __restrict__ ii_W) {
    __shared__ float4 s_ii4[64 * 32];                      // 32 KB
    __shared__ __align__(16) float s_s[8][PB][64];         // 8 KB
    __shared__ float4 s_i1b[8][PB][16];                    // 8 KB

    int tid = threadIdx.x;
    int lane = tid & 31;
    int wid = tid >> 5;

    for (int t = tid; t < 64 * 32; t += 256)
        s_ii4[t] = __ldg(((const float4*)ii_W) + t);
    __syncthreads();

    const int NG = N_PAIRS / (8 * PB);
    for (int g = blockIdx.x; g < NG; g += gridDim.x) {
        int qbase = (g * 8 + wid) * PB;
        int pr[PB], ii_[PB], jj_[PB];
        #pragma unroll
        for (int pp = 0; pp < PB; pp++) {
            pr[pp] = __ldg(&g_perm[qbase + pp]);
            int2 ij = __ldg((const int2*)ind2 + pr[pp]);
            ii_[pp] = ij.x; jj_[pp] = ij.y;
        }

        // ---- phase A per pair: s = sum_b tanh(A[i]+B[j]) * basis
        #pragma unroll
        for (int pp = 0; pp < PB; pp++) {
            int p = pr[pp];
            const float2* basf = (const float2*)(basis + (size_t)p * 10);
            const float4* Ar = (const float4*)(g_A + (size_t)ii_[pp] * 640);
            const float4* Br = (const float4*)(g_B + (size_t)jj_[pp] * 640);
            float sum0 = 0.f, sum1 = 0.f;
            #pragma unroll
            for (int b2i = 0; b2i < 5; b2i++) {
                float4 a4 = __ldg(Ar + b2i * 32 + lane);
                float4 b4 = __ldg(Br + b2i * 32 + lane);
                float2 bb = __ldg(basf + b2i);
                float t0 = tanh_hw(a4.x + b4.x);
                float t1 = tanh_hw(a4.y + b4.y);
                float t2 = tanh_hw(a4.z + b4.z);
                float t3 = tanh_hw(a4.w + b4.w);
                sum0 = fmaf(t0, bb.x, sum0);
                sum0 = fmaf(t1, bb.y, sum0);
                sum1 = fmaf(t2, bb.x, sum1);
                sum1 = fmaf(t3, bb.y, sum1);
            }
            *(float2*)&s_s[wid][pp][2 * lane] = make_float2(sum0, sum1);
        }
        __syncwarp();

        // ---- phase B: i_pair = tanh(s @ ii_W), weights shared across PB
        float4 acc[PB];
        #pragma unroll
        for (int pp = 0; pp < PB; pp++) acc[pp] = make_float4(0.f, 0.f, 0.f, 0.f);
        #pragma unroll
        for (int c4 = 0; c4 < 16; c4++) {
            float4 w0 = s_ii4[(4 * c4 + 0) * 32 + lane];
            float4 w1 = s_ii4[(4 * c4 + 1) * 32 + lane];
            float4 w2 = s_ii4[(4 * c4 + 2) * 32 + lane];
            float4 w3 = s_ii4[(4 * c4 + 3) * 32 + lane];
            #pragma unroll
            for (int pp = 0; pp < PB; pp++) {
                float4 sv = ((const float4*)s_s[wid][pp])[c4];
                acc[pp].x = fmaf(sv.x, w0.x, acc[pp].x); acc[pp].y = fmaf(sv.x, w0.y, acc[pp].y);
                acc[pp].z = fmaf(sv.x, w0.z, acc[pp].z); acc[pp].w = fmaf(sv.x, w0.w, acc[pp].w);
                acc[pp].x = fmaf(sv.y, w1.x, acc[pp].x); acc[pp].y = fmaf(sv.y, w1.y, acc[pp].y);
                acc[pp].z = fmaf(sv.y, w1.z, acc[pp].z); acc[pp].w = fmaf(sv.y, w1.w, acc[pp].w);
                acc[pp].x = fmaf(sv.z, w2.x, acc[pp].x); acc[pp].y = fmaf(sv.z, w2.y, acc[pp].y);
                acc[pp].z = fmaf(sv.z, w2.z, acc[pp].z); acc[pp].w = fmaf(sv.z, w2.w, acc[pp].w);
                acc[pp].x = fmaf(sv.w, w3.x, acc[pp].x); acc[pp].y = fmaf(sv.w, w3.y, acc[pp].y);
                acc[pp].z = fmaf(sv.w, w3.z, acc[pp].z); acc[pp].w = fmaf(sv.w, w3.w, acc[pp].w);
            }
        }
        // p1 segment-sum with flush-on-i-change merging
        {
            float4 accP1 = make_float4(0.f, 0.f, 0.f, 0.f);
            #pragma unroll
            for (int pp = 0; pp < PB; pp++) {
                float4 ip;
                ip.x = fast_tanh(acc[pp].x);
                ip.y = fast_tanh(acc[pp].y);
                ip.z = fast_tanh(acc[pp].z);
                ip.w = fast_tanh(acc[pp].w);
                accP1.x += ip.x; accP1.y += ip.y;
                accP1.z += ip.z; accP1.w += ip.w;
                bool flush = (pp == PB - 1) || (ii_[pp + 1] != ii_[pp]);
                if (flush) {
                    red_add_v4(g_p1scat + (size_t)ii_[pp] * 128 + 4 * lane, accP1);
                    accP1 = make_float4(0.f, 0.f, 0.f, 0.f);
                }
                if (lane >= 16) s_i1b[wid][pp][lane - 16] = ip;
            }
        }
        __syncwarp();

        // ---- phases C+D per pair, p3 accumulated + flushed on i-change
        {
            float4 accA = make_float4(0.f, 0.f, 0.f, 0.f);   // t = lane (x=0,1)
            float4 accBv = make_float4(0.f, 0.f, 0.f, 0.f);  // t = lane+32 (x=2, lane<16)
            #pragma unroll
            for (int pp = 0; pp < PB; pp++) {
                int p = pr[pp];
                int i = ii_[pp], j = jj_[pp];
                float d0 = __ldg(&d3[3 * p + 0]);
                float d1 = __ldg(&d3[3 * p + 1]);
                float d2 = __ldg(&d3[3 * p + 2]);
                float fc = __ldg(&fc_edge[p]);
                float4 v4 = __ldg((const float4*)g_v + i);
                float proj = v4.x * d0 + v4.y * d1 + v4.z * d2;
                float wx = v4.x - proj * d0, wy = v4.y - proj * d1, wz = v4.z - proj * d2;
                float w2 = wx * wx + wy * wy + wz * wz;
                float g_deg = __fdividef(w2, w2 + 1e-4f);
                float rs = rsqrtf(w2 + 1e-6f);
                float tb = g_deg * fc * fc;
                float sc = rs * g_deg * tb;
                float term0 = d0 + wx * sc;
                float term1 = d1 + wy * sc;
                float term2 = d2 + wz * sc;

                const float4* p3j = (const float4*)(p3 + (size_t)j * 192);
                {
                    int x = lane >> 4;
                    int m = lane & 15;
                    float4 gg = s_i1b[wid][pp][m];
                    float4 pj = __ldg(&p3j[x * 16 + m]);
                    float tm = (x == 0) ? term0 : term1;
                    accA.x = fmaf(gg.x, pj.x + tm, accA.x);
                    accA.y = fmaf(gg.y, pj.y + tm, accA.y);
                    accA.z = fmaf(gg.z, pj.z + tm, accA.z);
                    accA.w = fmaf(gg.w, pj.w + tm, accA.w);
                }
                if (lane < 16) {
                    int m = lane;
                    float4 gg = s_i1b[wid][pp][m];
                    float4 pj = __ldg(&p3j[2 * 16 + m]);
                    accBv.x = fmaf(gg.x, pj.x + term2, accBv.x);
                    accBv.y = fmaf(gg.y, pj.y + term2, accBv.y);
                    accBv.z = fmaf(gg.z, pj.z + term2, accBv.z);
                    accBv.w = fmaf(gg.w, pj.w + term2, accBv.w);
                }
                bool flush = (pp == PB - 1) || (ii_[pp + 1] != ii_[pp]);
                if (flush) {
                    float* accBase = g_p3acc + (size_t)i * 192;
                    int x = lane >> 4;
                    int m = lane & 15;
                    red_add_v4(accBase + x * 64 + 4 * m, accA);
                    if (lane < 16)
                        red_add_v4(accBase + 2 * 64 + 4 * lane, accBv);
                    accA = make_float4(0.f, 0.f, 0.f, 0.f);
                    accBv = make_float4(0.f, 0.f, 0.f, 0.f);
                }
            }
        }
    }
}

// ---------------- kernel F: atom finalize (32 atoms/block, 8-atom reg block) --
__global__ void __launch_bounds__(256) k_final(
        const float* __restrict__ postW1,
        const float* __restrict__ postW2,
        const float* __restrict__ eqW,
        const float* __restrict__ q1W1,
        const float* __restrict__ q1b1,
        const float* __restrict__ q1W2,
        const float* __restrict__ q1b2,
        float* __restrict__ out) {
    __shared__ float s_cat[32][128];
    __shared__ float s_acc[32][192];
    __shared__ float s_b[32][64];

    int tid = threadIdx.x;
    int o = tid & 63;
    int g = tid >> 6;
    int a_base = blockIdx.x * 32;
    float4 z4 = make_float4(0.f, 0.f, 0.f, 0.f);

    for (int e = tid; e < 32 * 32; e += 256) {
        int a = e >> 5, c4 = e & 31;
        int atom = a_base + a;
        ((float4*)s_cat[a])[c4] = (atom < N_ATOMS)
            ? __ldg((const float4*)(g_p1scat + (size_t)atom * 128) + c4) : z4;
    }
    for (int e = tid; e < 32 * 48; e += 256) {
        int a = e / 48, c4 = e % 48;
        int atom = a_base + a;
        ((float4*)s_acc[a])[c4] = (atom < N_ATOMS)
            ? __ldg((const float4*)(g_p3acc + (size_t)atom * 192) + c4) : z4;
    }
    __syncthreads();

    // phase1: t1 = tanh(scat @ postW1) -> s_b
    {
        float accv[8];
        #pragma unroll
        for (int u = 0; u < 8; u++) accv[u] = 0.f;
        for (int c = 0; c < 128; c++) {
            float w = __ldg(&postW1[c * 64 + o]);
            #pragma unroll
            for (int u = 0; u < 8; u++)
                accv[u] = fmaf(s_cat[8 * g + u][c], w, accv[u]);
        }
        __syncthreads();
        #pragma unroll
        for (int u = 0; u < 8; u++) s_b[8 * g + u][o] = fast_tanh(accv[u]);
    }
    __syncthreads();

    // phase2: p1_new = tanh(t1 @ postW2) -> s_cat[:, 0:64]
    {
        float accv[8];
        #pragma unroll
        for (int u = 0; u < 8; u++) accv[u] = 0.f;
        for (int c = 0; c < 64; c++) {
            float w = __ldg(&postW2[c * 64 + o]);
            #pragma unroll
            for (int u = 0; u < 8; u++)
                accv[u] = fmaf(s_b[8 * g + u][c], w, accv[u]);
        }
        #pragma unroll
        for (int u = 0; u < 8; u++) s_cat[8 * g + u][o] = fast_tanh(accv[u]);
    }

    // phase3: p3n (regs) + dotted -> s_cat[:, 64:128]
    float p3n[3][8];
    #pragma unroll
    for (int x = 0; x < 3; x++) {
        float accv[8];
        #pragma unroll
        for (int u = 0; u < 8; u++) accv[u] = 0.f;
        for (int c = 0; c < 64; c++) {
            float w = __ldg(&eqW[c * 64 + o]);
            #pragma unroll
            for (int u = 0; u < 8; u++)
                accv[u] = fmaf(s_acc[8 * g + u][x * 64 + c], w, accv[u]);
        }
        #pragma unroll
        for (int u = 0; u < 8; u++) p3n[x][u] = accv[u];
    }
    #pragma unroll
    for (int u = 0; u < 8; u++)
        s_cat[8 * g + u][64 + o] = p3n[0][u] * p3n[0][u] +
                                   p3n[1][u] * p3n[1][u] +
                                   p3n[2][u] * p3n[2][u];
    __syncthreads();

    // phase4: h2a = tanh(cat @ q1W1 + b1) -> s_b
    {
        float accv[8];
        float bias = __ldg(&q1b1[o]);
        #pragma unroll
        for (int u = 0; u < 8; u++) accv[u] = bias;
        for (int c = 0; c < 128; c++) {
            float w = __ldg(&q1W1[c * 64 + o]);
            #pragma unroll
            for (int u = 0; u < 8; u++)
                accv[u] = fmaf(s_cat[8 * g + u][c], w, accv[u]);
        }
        __syncthreads();
        #pragma unroll
        for (int u = 0; u < 8; u++) s_b[8 * g + u][o] = fast_tanh(accv[u]);
    }
    __syncthreads();

    // phase5: h2 = tanh(h2a @ q1W2 + b2); write outputs
    {
        float h0[8], h1[8];
        float bias0 = __ldg(&q1b2[o]);
        float bias1 = __ldg(&q1b2[o + 64]);
        #pragma unroll
        for (int u = 0; u < 8; u++) { h0[u] = bias0; h1[u] = bias1; }
        for (int c = 0; c < 64; c++) {
            float w0 = __ldg(&q1W2[c * 128 + o]);
            float w1 = __ldg(&q1W2[c * 128 + o + 64]);
            #pragma unroll
            for (int u = 0; u < 8; u++) {
                float v = s_b[8 * g + u][c];
                h0[u] = fmaf(v, w0, h0[u]);
                h1[u] = fmaf(v, w1, h1[u]);
            }
        }
        #pragma unroll
        for (int u = 0; u < 8; u++) {
            int atom = a_base + 8 * g + u;
            if (atom < N_ATOMS) {
                float g1 = fast_tanh(h0[u]);
                float g3 = fast_tanh(h1[u]);
                out[(size_t)atom * 64 + o] = g1;
                float* o3 = out + (size_t)N_ATOMS * 64 + (size_t)atom * 192;
                #pragma unroll
                for (int x = 0; x < 3; x++)
                    o3[x * 64 + o] = p3n[x][u] * g3;
            }
        }
    }
}

// ---------------- launch ------------------------------------------------------
extern "C" void kernel_launch(void* const* d_in, const int* in_sizes, int n_in,
                              void* d_out, int out_size) {
    const int*   ind2    = (const int*)d_in[0];
    const float* p1      = (const float*)d_in[1];
    const float* p3      = (const float*)d_in[2];
    const float* basis   = (const float*)d_in[3];
    const float* d3      = (const float*)d_in[4];
    const float* fc_edge = (const float*)d_in[5];
    const float* ppreW1  = (const float*)d_in[6];
    const float* ppreb1  = (const float*)d_in[7];
    const float* ppreW2  = (const float*)d_in[8];
    const float* ppreb2  = (const float*)d_in[9];
    const float* piW     = (const float*)d_in[10];
    const float* pib     = (const float*)d_in[11];
    const float* iiW     = (const float*)d_in[12];
    const float* postW1  = (const float*)d_in[13];
    const float* postW2  = (const float*)d_in[14];
    const float* eqW     = (const float*)d_in[15];
    const float* q1W1    = (const float*)d_in[16];
    const float* q1b1    = (const float*)d_in[17];
    const float* q1W2    = (const float*)d_in[18];
    const float* q1b2    = (const float*)d_in[19];
    float* out = (float*)d_out;

    k_hzero<<<(N_ATOMS + 255) / 256, 256>>>();
    k_zero<<<512, 256>>>();
    k_hist<<<(N_PAIRS + 255) / 256, 256>>>(ind2);
    k_scan<<<1, 1024>>>();
    k_scatter<<<(N_PAIRS + 255) / 256, 256>>>(ind2);
    k_vscat<<<(N_PAIRS + 255) / 256, 256>>>(ind2, d3, fc_edge);
    k_ab1<<<(N_ATOMS + 31) / 32, 256>>>(p1, ppreW1, ppreb1, ppreW2, ppreb2);
    {
        dim3 grid((N_ATOMS + 127) / 128, 20);
        k_ab2<<<grid, 256>>>(piW, pib);
    }
    k_pairs<<<592, 256>>>(ind2, basis, d3, fc_edge, p3, iiW);
    k_final<<<(N_ATOMS + 31) / 32, 256>>>(postW1, postW2, eqW, q1W1, q1b1, q1W2, q1b2, out);
}